// round 2
// baseline (speedup 1.0000x reference)
#include <cuda_runtime.h>
#include <cuda_fp16.h>
#include <cstdint>

// Problem constants
#define MDIM 32
#define KDIM 8192
#define NDIM 28672
#define N_TILE 64          // n-columns per CTA (4 warps x 16)
#define K_CHUNK 256        // act K-chunk staged in SMEM (as fp16)
#define APAD 8             // half-element pad per act row (16B -> conflict-free ldmatrix)
#define THREADS 128

// ---------------------------------------------------------------------------
// mma.sync m16n8k16 fp16 -> fp32
__device__ __forceinline__ void mma16816(float c[4], const uint32_t a[4],
                                         uint32_t b0, uint32_t b1) {
    asm volatile(
        "mma.sync.aligned.m16n8k16.row.col.f32.f16.f16.f32 "
        "{%0,%1,%2,%3}, {%4,%5,%6,%7}, {%8,%9}, {%0,%1,%2,%3};"
        : "+f"(c[0]), "+f"(c[1]), "+f"(c[2]), "+f"(c[3])
        : "r"(a[0]), "r"(a[1]), "r"(a[2]), "r"(a[3]), "r"(b0), "r"(b1));
}

// ldmatrix x4 (non-transposed) for A fragments
__device__ __forceinline__ void ldsm_x4(uint32_t a[4], uint32_t smem_addr) {
    asm volatile(
        "ldmatrix.sync.aligned.m8n8.x4.shared.b16 {%0,%1,%2,%3}, [%4];"
        : "=r"(a[0]), "=r"(a[1]), "=r"(a[2]), "=r"(a[3])
        : "r"(smem_addr));
}

// Convert two int32 weights (values in [-127,127]) into packed half2 {w0, w1}.
// PRMT places the low bytes at result bytes 0 and 2; LOP3 computes
// (t & 0x00FF00FF) ^ 0x64806480 == fp16 bits of (v+1152); HSUB2 removes the
// 1152 bias exactly (all values integer-exact in fp16).
__device__ __forceinline__ uint32_t cvt_w2(int w0, int w1) {
    uint32_t t, h;
    asm("prmt.b32 %0, %1, %2, 0x0400;" : "=r"(t) : "r"(w0), "r"(w1));
    asm("lop3.b32 %0, %1, %2, %3, 0x6A;"            // (a & b) ^ c
        : "=r"(h) : "r"(t), "n"(0x00FF00FF), "n"(0x64806480));
    const uint32_t bias = 0x64806480u;               // half2(1152, 1152)
    __half2 hv = __hsub2(*reinterpret_cast<__half2*>(&h),
                         *reinterpret_cast<const __half2*>(&bias));
    return *reinterpret_cast<uint32_t*>(&hv);
}

// ---------------------------------------------------------------------------
__global__ void __launch_bounds__(THREADS)
dq_gemm_kernel(const float* __restrict__ act,     // f32 (fp16 values widened)
               const int*   __restrict__ weight,  // int32 (int8 values)
               const float* __restrict__ scale,   // f32
               float*       __restrict__ out) {   // f32 (emit fp16-rounded)
    __shared__ __half sA[MDIM][K_CHUNK + APAD];

    const int tid  = threadIdx.x;
    const int warp = tid >> 5;
    const int lane = tid & 31;
    const int gid  = lane >> 2;   // 0..7  (fragment column / C row)
    const int tig  = lane & 3;    // 0..3  (fragment row-pair)

    const int n_warp = blockIdx.x * N_TILE + warp * 16;

    float acc[2][2][4];
#pragma unroll
    for (int i = 0; i < 2; i++)
#pragma unroll
        for (int j = 0; j < 2; j++)
#pragma unroll
            for (int c = 0; c < 4; c++) acc[i][j][c] = 0.0f;

    // ldmatrix lane address pattern: row = lane&15, col-base = 8*(lane>>4)
    const int lrow = lane & 15;
    const int lcol = (lane >> 4) * 8;
    const uint32_t sA_base = (uint32_t)__cvta_generic_to_shared(&sA[0][0]);
    const uint32_t rowbytes = (K_CHUNK + APAD) * 2;
    const uint32_t addrA0 = sA_base + lrow * rowbytes + lcol * 2;          // m-tile 0
    const uint32_t addrA1 = sA_base + (16 + lrow) * rowbytes + lcol * 2;   // m-tile 1

    // Per-thread weight base: rows offset 2*tig, column n_warp + gid (+nt*8)
    const int* wthread = weight + (size_t)(2 * tig) * NDIM + n_warp + gid;

    for (int kc = 0; kc < KDIM; kc += K_CHUNK) {
        // --- cooperative act chunk load: 32 rows x 256 f32 -> fp16 in SMEM
        // (f32 values are exactly-representable fp16; conversion is lossless)
#pragma unroll
        for (int i = tid; i < MDIM * (K_CHUNK / 4); i += THREADS) {
            const int r = i >> 6;           // K_CHUNK/4 == 64
            const int c = i & 63;
            const float4 v = *reinterpret_cast<const float4*>(
                act + (size_t)r * KDIM + kc + c * 4);
            __half2* dst = reinterpret_cast<__half2*>(&sA[r][c * 4]);
            dst[0] = __floats2half2_rn(v.x, v.y);
            dst[1] = __floats2half2_rn(v.z, v.w);
        }
        __syncthreads();

#pragma unroll 4
        for (int ks = 0; ks < K_CHUNK; ks += 16) {
            uint32_t afrag0[4], afrag1[4];
            ldsm_x4(afrag0, addrA0 + ks * 2);
            ldsm_x4(afrag1, addrA1 + ks * 2);

            const int* wp = wthread + (size_t)(kc + ks) * NDIM;
#pragma unroll
            for (int nt = 0; nt < 2; nt++) {
                const int* w = wp + nt * 8;
                const int w0 = w[0];
                const int w1 = w[NDIM];
                const int w2 = w[8 * (size_t)NDIM];
                const int w3 = w[9 * (size_t)NDIM];
                const uint32_t b0 = cvt_w2(w0, w1);   // k rows 2tig, 2tig+1
                const uint32_t b1 = cvt_w2(w2, w3);   // k rows 2tig+8, 2tig+9
                mma16816(acc[0][nt], afrag0, b0, b1);
                mma16816(acc[1][nt], afrag1, b0, b1);
            }
        }
        __syncthreads();
    }

    // --- epilogue: out = float( half( acc * scale[n] ) )  (match ref fp16 rounding)
#pragma unroll
    for (int mt = 0; mt < 2; mt++) {
#pragma unroll
        for (int nt = 0; nt < 2; nt++) {
            const int col = n_warp + nt * 8 + 2 * tig;
            const float sx = scale[col];
            const float sy = scale[col + 1];
            const int r0 = mt * 16 + gid;
#pragma unroll
            for (int half_row = 0; half_row < 2; half_row++) {
                const int r = r0 + half_row * 8;
                const float vx = acc[mt][nt][half_row * 2 + 0] * sx;
                const float vy = acc[mt][nt][half_row * 2 + 1] * sy;
                float2 o;
                o.x = __half2float(__float2half_rn(vx));
                o.y = __half2float(__float2half_rn(vy));
                *reinterpret_cast<float2*>(out + (size_t)r * NDIM + col) = o;
            }
        }
    }
}

// ---------------------------------------------------------------------------
extern "C" void kernel_launch(void* const* d_in, const int* in_sizes, int n_in,
                              void* d_out, int out_size) {
    const float* act    = (const float*)d_in[0];   // [32, 8192] f32
    const int*   weight = (const int*)d_in[1];     // [8192, 28672] int32
    const float* scale  = (const float*)d_in[2];   // [28672] f32
    float*       out    = (float*)d_out;           // [32, 28672] f32

    dq_gemm_kernel<<<NDIM / N_TILE, THREADS>>>(act, weight, scale, out);
}

// round 3
// speedup vs baseline: 1.6750x; 1.6750x over previous
#include <cuda_runtime.h>
#include <cuda_fp16.h>
#include <cstdint>

// Problem constants
#define MDIM 32
#define KDIM 8192
#define NDIM 28672
#define N_TILE 64          // n-columns per CTA (4 warps x 16)
#define K_CHUNK 256        // act K-chunk staged in SMEM (as fp16)
#define APAD 8             // half-element pad per act row (16B -> conflict-free ldmatrix)
#define THREADS 128
#define KSPLIT 4
#define K_PER_SPLIT (KDIM / KSPLIT)   // 2048

// Split-K partial accumulators (fp32, unscaled). 4 * 32 * 28672 * 4B = 14.7 MB.
__device__ float g_partial[KSPLIT][MDIM * NDIM];

// ---------------------------------------------------------------------------
// mma.sync m16n8k16 fp16 -> fp32
__device__ __forceinline__ void mma16816(float c[4], const uint32_t a[4],
                                         uint32_t b0, uint32_t b1) {
    asm volatile(
        "mma.sync.aligned.m16n8k16.row.col.f32.f16.f16.f32 "
        "{%0,%1,%2,%3}, {%4,%5,%6,%7}, {%8,%9}, {%0,%1,%2,%3};"
        : "+f"(c[0]), "+f"(c[1]), "+f"(c[2]), "+f"(c[3])
        : "r"(a[0]), "r"(a[1]), "r"(a[2]), "r"(a[3]), "r"(b0), "r"(b1));
}

// ldmatrix x4 (non-transposed) for A fragments
__device__ __forceinline__ void ldsm_x4(uint32_t a[4], uint32_t smem_addr) {
    asm volatile(
        "ldmatrix.sync.aligned.m8n8.x4.shared.b16 {%0,%1,%2,%3}, [%4];"
        : "=r"(a[0]), "=r"(a[1]), "=r"(a[2]), "=r"(a[3])
        : "r"(smem_addr));
}

// Convert two int32 weights (values in [-127,127]) into packed half2 {w0, w1}.
// PRMT places low bytes at result bytes 0/2; LOP3 computes
// (t & 0x00FF00FF) ^ 0x64806480 == fp16 bits of (v+1152); HSUB2 removes the
// 1152 bias exactly.
__device__ __forceinline__ uint32_t cvt_w2(int w0, int w1) {
    uint32_t t, h;
    asm("prmt.b32 %0, %1, %2, 0x0400;" : "=r"(t) : "r"(w0), "r"(w1));
    asm("lop3.b32 %0, %1, %2, %3, 0x6A;"            // (a & b) ^ c
        : "=r"(h) : "r"(t), "n"(0x00FF00FF), "n"(0x64806480));
    const uint32_t bias = 0x64806480u;               // half2(1152, 1152)
    __half2 hv = __hsub2(*reinterpret_cast<__half2*>(&h),
                         *reinterpret_cast<const __half2*>(&bias));
    return *reinterpret_cast<uint32_t*>(&hv);
}

// ---------------------------------------------------------------------------
__global__ void __launch_bounds__(THREADS, 8)
dq_gemm_partial_kernel(const float* __restrict__ act,     // f32 (fp16 values)
                       const int*   __restrict__ weight)  // int32 (int8 values)
{
    __shared__ __half sA[MDIM][K_CHUNK + APAD];

    const int tid  = threadIdx.x;
    const int warp = tid >> 5;
    const int lane = tid & 31;
    const int gid  = lane >> 2;   // 0..7
    const int tig  = lane & 3;    // 0..3

    const int n_warp = blockIdx.x * N_TILE + warp * 16;
    const int kz     = blockIdx.y;                  // split-K index
    const int kbase  = kz * K_PER_SPLIT;

    float acc[2][2][4];
#pragma unroll
    for (int i = 0; i < 2; i++)
#pragma unroll
        for (int j = 0; j < 2; j++)
#pragma unroll
            for (int c = 0; c < 4; c++) acc[i][j][c] = 0.0f;

    const int lrow = lane & 15;
    const int lcol = (lane >> 4) * 8;
    const uint32_t sA_base = (uint32_t)__cvta_generic_to_shared(&sA[0][0]);
    const uint32_t rowbytes = (K_CHUNK + APAD) * 2;
    const uint32_t addrA0 = sA_base + lrow * rowbytes + lcol * 2;
    const uint32_t addrA1 = sA_base + (16 + lrow) * rowbytes + lcol * 2;

    const int* wthread = weight + (size_t)(2 * tig) * NDIM + n_warp + gid;

    for (int kc = kbase; kc < kbase + K_PER_SPLIT; kc += K_CHUNK) {
        // cooperative act chunk load: 32 rows x 256 f32 -> fp16 in SMEM (lossless)
#pragma unroll
        for (int i = tid; i < MDIM * (K_CHUNK / 4); i += THREADS) {
            const int r = i >> 6;           // K_CHUNK/4 == 64
            const int c = i & 63;
            const float4 v = *reinterpret_cast<const float4*>(
                act + (size_t)r * KDIM + kc + c * 4);
            __half2* dst = reinterpret_cast<__half2*>(&sA[r][c * 4]);
            dst[0] = __floats2half2_rn(v.x, v.y);
            dst[1] = __floats2half2_rn(v.z, v.w);
        }
        __syncthreads();

#pragma unroll 4
        for (int ks = 0; ks < K_CHUNK; ks += 16) {
            uint32_t afrag0[4], afrag1[4];
            ldsm_x4(afrag0, addrA0 + ks * 2);
            ldsm_x4(afrag1, addrA1 + ks * 2);

            const int* wp = wthread + (size_t)(kc + ks) * NDIM;
#pragma unroll
            for (int nt = 0; nt < 2; nt++) {
                const int* w = wp + nt * 8;
                const int w0 = w[0];
                const int w1 = w[NDIM];
                const int w2 = w[8 * (size_t)NDIM];
                const int w3 = w[9 * (size_t)NDIM];
                const uint32_t b0 = cvt_w2(w0, w1);
                const uint32_t b1 = cvt_w2(w2, w3);
                mma16816(acc[0][nt], afrag0, b0, b1);
                mma16816(acc[1][nt], afrag1, b0, b1);
            }
        }
        __syncthreads();
    }

    // write unscaled partials
    float* part = g_partial[kz];
#pragma unroll
    for (int mt = 0; mt < 2; mt++) {
#pragma unroll
        for (int nt = 0; nt < 2; nt++) {
            const int col = n_warp + nt * 8 + 2 * tig;
            const int r0 = mt * 16 + gid;
#pragma unroll
            for (int hr = 0; hr < 2; hr++) {
                const int r = r0 + hr * 8;
                float2 o;
                o.x = acc[mt][nt][hr * 2 + 0];
                o.y = acc[mt][nt][hr * 2 + 1];
                *reinterpret_cast<float2*>(part + (size_t)r * NDIM + col) = o;
            }
        }
    }
}

// ---------------------------------------------------------------------------
// Reduce split-K partials, apply scale, round through fp16, emit f32.
__global__ void __launch_bounds__(256)
reduce_kernel(const float* __restrict__ scale, float* __restrict__ out) {
    const int idx = blockIdx.x * blockDim.x + threadIdx.x;   // per float4
    const size_t off = (size_t)idx * 4;
    if (off >= (size_t)MDIM * NDIM) return;

    float4 s0 = *reinterpret_cast<const float4*>(&g_partial[0][off]);
    float4 s1 = *reinterpret_cast<const float4*>(&g_partial[1][off]);
    float4 s2 = *reinterpret_cast<const float4*>(&g_partial[2][off]);
    float4 s3 = *reinterpret_cast<const float4*>(&g_partial[3][off]);

    const int col = (int)(off % NDIM);
    const float4 sc = *reinterpret_cast<const float4*>(scale + col);

    float4 o;
    o.x = __half2float(__float2half_rn((s0.x + s1.x + s2.x + s3.x) * sc.x));
    o.y = __half2float(__float2half_rn((s0.y + s1.y + s2.y + s3.y) * sc.y));
    o.z = __half2float(__float2half_rn((s0.z + s1.z + s2.z + s3.z) * sc.z));
    o.w = __half2float(__float2half_rn((s0.w + s1.w + s2.w + s3.w) * sc.w));
    *reinterpret_cast<float4*>(out + off) = o;
}

// ---------------------------------------------------------------------------
extern "C" void kernel_launch(void* const* d_in, const int* in_sizes, int n_in,
                              void* d_out, int out_size) {
    const float* act    = (const float*)d_in[0];   // [32, 8192] f32
    const int*   weight = (const int*)d_in[1];     // [8192, 28672] int32
    const float* scale  = (const float*)d_in[2];   // [28672] f32
    float*       out    = (float*)d_out;           // [32, 28672] f32

    dim3 grid(NDIM / N_TILE, KSPLIT);
    dq_gemm_partial_kernel<<<grid, THREADS>>>(act, weight);

    const int total4 = (MDIM * NDIM) / 4;          // 229376
    reduce_kernel<<<(total4 + 255) / 256, 256>>>(scale, out);
}

// round 4
// speedup vs baseline: 1.9432x; 1.1601x over previous
#include <cuda_runtime.h>
#include <cuda_fp16.h>
#include <cstdint>

// Problem constants
#define MDIM 32
#define KDIM 8192
#define NDIM 28672
#define N_TILE 64            // n-columns per CTA (4 warps x 16)
#define K_CHUNK 256          // act K-chunk staged in SMEM (as fp16)
#define APAD 8               // pad per act row -> conflict-free ldmatrix
#define THREADS 128
#define KSPLIT 8
#define K_PER_SPLIT (KDIM / KSPLIT)       // 1024
#define S_K 32                            // weight k-rows per pipeline stage
#define STAGES_PER_CHUNK (K_CHUNK / S_K)  // 8
#define TOTAL_STAGES (K_PER_SPLIT / S_K)  // 32

// Split-K partial accumulators (fp32, unscaled). 8 * 32 * 28672 * 4B = 29.4 MB.
__device__ float g_partial[KSPLIT][MDIM * NDIM];

// ---------------------------------------------------------------------------
__device__ __forceinline__ void mma16816(float c[4], const uint32_t a[4],
                                         uint32_t b0, uint32_t b1) {
    asm volatile(
        "mma.sync.aligned.m16n8k16.row.col.f32.f16.f16.f32 "
        "{%0,%1,%2,%3}, {%4,%5,%6,%7}, {%8,%9}, {%0,%1,%2,%3};"
        : "+f"(c[0]), "+f"(c[1]), "+f"(c[2]), "+f"(c[3])
        : "r"(a[0]), "r"(a[1]), "r"(a[2]), "r"(a[3]), "r"(b0), "r"(b1));
}

__device__ __forceinline__ void ldsm_x4(uint32_t a[4], uint32_t smem_addr) {
    asm volatile(
        "ldmatrix.sync.aligned.m8n8.x4.shared.b16 {%0,%1,%2,%3}, [%4];"
        : "=r"(a[0]), "=r"(a[1]), "=r"(a[2]), "=r"(a[3])
        : "r"(smem_addr));
}

__device__ __forceinline__ void ldsm_x4_trans(uint32_t a[4], uint32_t smem_addr) {
    asm volatile(
        "ldmatrix.sync.aligned.m8n8.x4.trans.shared.b16 {%0,%1,%2,%3}, [%4];"
        : "=r"(a[0]), "=r"(a[1]), "=r"(a[2]), "=r"(a[3])
        : "r"(smem_addr));
}

// Two int32 weights (in [-127,127]) -> packed half2 {w0, w1}. Exact.
__device__ __forceinline__ uint32_t cvt_w2(int w0, int w1) {
    uint32_t t, h;
    asm("prmt.b32 %0, %1, %2, 0x0400;" : "=r"(t) : "r"(w0), "r"(w1));
    asm("lop3.b32 %0, %1, %2, %3, 0x6A;"            // (a & b) ^ c
        : "=r"(h) : "r"(t), "n"(0x00FF00FF), "n"(0x64806480));
    const uint32_t bias = 0x64806480u;               // half2(1152, 1152)
    __half2 hv = __hsub2(*reinterpret_cast<__half2*>(&h),
                         *reinterpret_cast<const __half2*>(&bias));
    return *reinterpret_cast<uint32_t*>(&hv);
}

// ---------------------------------------------------------------------------
__global__ void __launch_bounds__(THREADS, 8)
dq_gemm_partial_kernel(const float* __restrict__ act,     // f32 (fp16 values)
                       const int*   __restrict__ weight)  // int32 (int8 values)
{
    __shared__ __half sA[MDIM][K_CHUNK + APAD];
    // Weight tile, double-buffered: [2][S_K rows][64 cols] fp16, 128B per row,
    // XOR-swizzled by (k%8)*16 bytes for conflict-free ldmatrix/STS.
    __shared__ __half sW[2][S_K * 64];

    const int tid  = threadIdx.x;
    const int warp = tid >> 5;
    const int lane = tid & 31;

    const int nblk  = blockIdx.x * N_TILE;
    const int kz    = blockIdx.y;
    const int kbase = kz * K_PER_SPLIT;

    float acc[2][2][4];
#pragma unroll
    for (int i = 0; i < 2; i++)
#pragma unroll
        for (int j = 0; j < 2; j++)
#pragma unroll
            for (int c = 0; c < 4; c++) acc[i][j][c] = 0.0f;

    // --- A-side ldmatrix addresses
    const int lrow = lane & 15;
    const int lcol = (lane >> 4) * 8;
    const uint32_t sA_base = (uint32_t)__cvta_generic_to_shared(&sA[0][0]);
    const uint32_t rowbytesA = (K_CHUNK + APAD) * 2;
    const uint32_t addrA0 = sA_base + lrow * rowbytesA + lcol * 2;         // m 0-15
    const uint32_t addrA1 = sA_base + (16 + lrow) * rowbytesA + lcol * 2;  // m 16-31

    // --- B-side ldmatrix.x4.trans address (per lane)
    // tiles: t0=(k0-7,n0-7) t1=(k8-15,n0-7) t2=(k0-7,n8-15) t3=(k8-15,n8-15)
    const uint32_t sW_base = (uint32_t)__cvta_generic_to_shared(&sW[0][0]);
    const int bt = lane >> 3;          // 0..3
    const int br = lane & 7;           // row within 8x8 tile = k%8
    const int kl = (bt & 1) * 8 + br;  // local k row 0..15
    const int nbyte = warp * 32 + (bt >> 1) * 16;          // n offset in bytes
    const uint32_t addrB = sW_base + kl * 128 + (uint32_t)(nbyte ^ (br * 16));

    // --- weight LDG.128 addressing: thread handles rows (tid>>4)+8j, cols 4*(tid&15)
    const int trow = tid >> 4;         // 0..7
    const int tcol = (tid & 15) * 4;   // 0,4,...,60
    const int* wptr = weight + (size_t)trow * NDIM + nblk + tcol;
    // STS offsets: swizzle constant across j (row%8 == trow)
    const uint32_t swz = (uint32_t)((8 * (tid & 15)) ^ (trow * 16));
    char* sW_raw = reinterpret_cast<char*>(&sW[0][0]);

    int4 wr[4];

    // helper lambdas -------------------------------------------------------
    auto ldg_stage = [&](int k) {
        const int* p = wptr + (size_t)k * NDIM;
#pragma unroll
        for (int j = 0; j < 4; j++)
            wr[j] = *reinterpret_cast<const int4*>(p + (size_t)(8 * j) * NDIM);
    };
    auto sts_stage = [&](int buf) {
        char* base = sW_raw + buf * (S_K * 64 * 2);
#pragma unroll
        for (int j = 0; j < 4; j++) {
            uint2 h;
            h.x = cvt_w2(wr[j].x, wr[j].y);
            h.y = cvt_w2(wr[j].z, wr[j].w);
            *reinterpret_cast<uint2*>(base + (trow + 8 * j) * 128 + swz) = h;
        }
    };
    auto load_act = [&](int kc) {
#pragma unroll
        for (int i = tid; i < MDIM * (K_CHUNK / 4); i += THREADS) {
            const int r = i >> 6;           // K_CHUNK/4 == 64
            const int c = i & 63;
            const float4 v = *reinterpret_cast<const float4*>(
                act + (size_t)r * KDIM + kc + c * 4);
            __half2* dst = reinterpret_cast<__half2*>(&sA[r][c * 4]);
            dst[0] = __floats2half2_rn(v.x, v.y);
            dst[1] = __floats2half2_rn(v.z, v.w);
        }
    };
    auto compute_stage = [&](int buf, int choff) {
        const uint32_t aoff = (uint32_t)choff * 2;
        const uint32_t boff = (uint32_t)buf * (S_K * 64 * 2);
#pragma unroll
        for (int kk = 0; kk < S_K; kk += 16) {
            uint32_t afrag0[4], afrag1[4], bfrag[4];
            ldsm_x4(afrag0, addrA0 + aoff + kk * 2);
            ldsm_x4(afrag1, addrA1 + aoff + kk * 2);
            ldsm_x4_trans(bfrag, addrB + boff + kk * 128);
            mma16816(acc[0][0], afrag0, bfrag[0], bfrag[1]);
            mma16816(acc[1][0], afrag1, bfrag[0], bfrag[1]);
            mma16816(acc[0][1], afrag0, bfrag[2], bfrag[3]);
            mma16816(acc[1][1], afrag1, bfrag[2], bfrag[3]);
        }
    };
    // ----------------------------------------------------------------------

    // prologue: stage 0 into sW[0], stage 1 into regs, act chunk 0
    ldg_stage(kbase);
    sts_stage(0);
    ldg_stage(kbase + S_K);
    load_act(kbase);
    __syncthreads();

    int buf = 0;
#pragma unroll 1
    for (int st = 0; st < TOTAL_STAGES; st++) {
        if (st + 1 < TOTAL_STAGES) sts_stage(buf ^ 1);      // stage st+1
        if (st + 2 < TOTAL_STAGES) ldg_stage(kbase + (st + 2) * S_K);
        compute_stage(buf, (st % STAGES_PER_CHUNK) * S_K);
        buf ^= 1;
        if (((st + 1) % STAGES_PER_CHUNK == 0) && (st + 1 < TOTAL_STAGES)) {
            __syncthreads();
            load_act(kbase + (st + 1) * S_K);   // next act chunk
            __syncthreads();
        } else {
            __syncthreads();
        }
    }

    // write unscaled partials
    const int gid = lane >> 2;
    const int tig = lane & 3;
    float* part = g_partial[kz];
#pragma unroll
    for (int mt = 0; mt < 2; mt++) {
#pragma unroll
        for (int nt = 0; nt < 2; nt++) {
            const int col = nblk + warp * 16 + nt * 8 + 2 * tig;
            const int r0 = mt * 16 + gid;
#pragma unroll
            for (int hr = 0; hr < 2; hr++) {
                const int r = r0 + hr * 8;
                float2 o;
                o.x = acc[mt][nt][hr * 2 + 0];
                o.y = acc[mt][nt][hr * 2 + 1];
                *reinterpret_cast<float2*>(part + (size_t)r * NDIM + col) = o;
            }
        }
    }
}

// ---------------------------------------------------------------------------
// Reduce split-K partials, apply scale, round through fp16, emit f32.
__global__ void __launch_bounds__(256)
reduce_kernel(const float* __restrict__ scale, float* __restrict__ out) {
    const int idx = blockIdx.x * blockDim.x + threadIdx.x;   // per float4
    const size_t off = (size_t)idx * 4;
    if (off >= (size_t)MDIM * NDIM) return;

    float4 s = *reinterpret_cast<const float4*>(&g_partial[0][off]);
#pragma unroll
    for (int p = 1; p < KSPLIT; p++) {
        const float4 q = *reinterpret_cast<const float4*>(&g_partial[p][off]);
        s.x += q.x; s.y += q.y; s.z += q.z; s.w += q.w;
    }

    const int col = (int)(off % NDIM);
    const float4 sc = *reinterpret_cast<const float4*>(scale + col);

    float4 o;
    o.x = __half2float(__float2half_rn(s.x * sc.x));
    o.y = __half2float(__float2half_rn(s.y * sc.y));
    o.z = __half2float(__float2half_rn(s.z * sc.z));
    o.w = __half2float(__float2half_rn(s.w * sc.w));
    *reinterpret_cast<float4*>(out + off) = o;
}

// ---------------------------------------------------------------------------
extern "C" void kernel_launch(void* const* d_in, const int* in_sizes, int n_in,
                              void* d_out, int out_size) {
    const float* act    = (const float*)d_in[0];   // [32, 8192] f32
    const int*   weight = (const int*)d_in[1];     // [8192, 28672] int32
    const float* scale  = (const float*)d_in[2];   // [28672] f32
    float*       out    = (float*)d_out;           // [32, 28672] f32

    dim3 grid(NDIM / N_TILE, KSPLIT);
    dq_gemm_partial_kernel<<<grid, THREADS>>>(act, weight);

    const int total4 = (MDIM * NDIM) / 4;          // 229376
    reduce_kernel<<<(total4 + 255) / 256, 256>>>(scale, out);
}

// round 5
// speedup vs baseline: 2.1738x; 1.1187x over previous
#include <cuda_runtime.h>
#include <cuda_fp16.h>
#include <cstdint>

// Problem constants
#define MDIM 32
#define KDIM 8192
#define NDIM 28672
#define N_TILE 64                 // n-columns per CTA (4 warps x 16)
#define THREADS 128
#define KSPLIT 4
#define K_PER_SPLIT (KDIM / KSPLIT)   // 2048
#define S_K 32                        // weight k-rows per pipeline stage
#define NBUF 4                        // cp.async ring depth
#define TOTAL_STAGES (K_PER_SPLIT / S_K)  // 64
#define K_CHUNK 256                   // act chunk (8 stages)
#define APAD 8
#define WPITCH 68                     // int32 words per weight row in SMEM (64 + 4 pad)

// Scratch: split-K fp32 partials (4 * 32 * 28672 * 4B = 14.7 MB) + fp16 act copy
__device__ float  g_partial[KSPLIT][MDIM * NDIM];
__device__ __half g_actH[MDIM * KDIM];

// ---------------------------------------------------------------------------
__device__ __forceinline__ void mma16816(float c[4], const uint32_t a[4],
                                         uint32_t b0, uint32_t b1) {
    asm volatile(
        "mma.sync.aligned.m16n8k16.row.col.f32.f16.f16.f32 "
        "{%0,%1,%2,%3}, {%4,%5,%6,%7}, {%8,%9}, {%0,%1,%2,%3};"
        : "+f"(c[0]), "+f"(c[1]), "+f"(c[2]), "+f"(c[3])
        : "r"(a[0]), "r"(a[1]), "r"(a[2]), "r"(a[3]), "r"(b0), "r"(b1));
}

__device__ __forceinline__ void ldsm_x4(uint32_t a[4], uint32_t smem_addr) {
    asm volatile(
        "ldmatrix.sync.aligned.m8n8.x4.shared.b16 {%0,%1,%2,%3}, [%4];"
        : "=r"(a[0]), "=r"(a[1]), "=r"(a[2]), "=r"(a[3])
        : "r"(smem_addr));
}

// Two int32 weights (in [-127,127]) -> packed half2 {w0, w1}. Exact.
__device__ __forceinline__ uint32_t cvt_w2(int w0, int w1) {
    uint32_t t, h;
    asm("prmt.b32 %0, %1, %2, 0x0400;" : "=r"(t) : "r"(w0), "r"(w1));
    asm("lop3.b32 %0, %1, %2, %3, 0x6A;"            // (a & b) ^ c
        : "=r"(h) : "r"(t), "n"(0x00FF00FF), "n"(0x64806480));
    const uint32_t bias = 0x64806480u;               // half2(1152, 1152)
    __half2 hv = __hsub2(*reinterpret_cast<__half2*>(&h),
                         *reinterpret_cast<const __half2*>(&bias));
    return *reinterpret_cast<uint32_t*>(&hv);
}

__device__ __forceinline__ void cp_async16(uint32_t smem_dst, const void* gsrc) {
    asm volatile("cp.async.cg.shared.global [%0], [%1], 16;\n"
                 :: "r"(smem_dst), "l"(gsrc));
}

// ---------------------------------------------------------------------------
__global__ void __launch_bounds__(THREADS)
dq_gemm_partial_kernel(const int* __restrict__ weight)   // int32 (int8 values)
{
    __shared__ __half sA[MDIM][K_CHUNK + APAD];
    __shared__ int    sW[NBUF][S_K * WPITCH];            // raw int32 weight tiles

    const int tid  = threadIdx.x;
    const int warp = tid >> 5;
    const int lane = tid & 31;
    const int gid  = lane >> 2;   // 0..7
    const int tig  = lane & 3;    // 0..3

    const int nblk  = blockIdx.x * N_TILE;
    const int kz    = blockIdx.y;
    const int kbase = kz * K_PER_SPLIT;

    float acc[2][2][4];
#pragma unroll
    for (int i = 0; i < 2; i++)
#pragma unroll
        for (int j = 0; j < 2; j++)
#pragma unroll
            for (int c = 0; c < 4; c++) acc[i][j][c] = 0.0f;

    // A-side ldmatrix addresses
    const int lrow = lane & 15;
    const int lcol = (lane >> 4) * 8;
    const uint32_t sA_base = (uint32_t)__cvta_generic_to_shared(&sA[0][0]);
    const uint32_t rowbytesA = (K_CHUNK + APAD) * 2;
    const uint32_t addrA0 = sA_base + lrow * rowbytesA + lcol * 2;         // m 0-15
    const uint32_t addrA1 = sA_base + (16 + lrow) * rowbytesA + lcol * 2;  // m 16-31

    // Weight cp.async addressing: thread -> rows (tid>>4)+8j, cols 4*(tid&15)
    const int trow = tid >> 4;          // 0..7
    const int tcol = (tid & 15) * 4;    // 0..60
    const uint32_t sW_base = (uint32_t)__cvta_generic_to_shared(&sW[0][0]);
    const uint32_t cp_dst0 = sW_base + (uint32_t)((trow * WPITCH + tcol) * 4);
    const int* wsrc = weight + (size_t)trow * NDIM + nblk + tcol;

    // B-fragment LDS base (int32 words within a buffer)
    const int boff = 2 * tig * WPITCH + warp * 16 + gid;

    auto cp_stage = [&](int k0, int buf) {
        const int* src = wsrc + (size_t)k0 * NDIM;
        const uint32_t dst = cp_dst0 + (uint32_t)buf * (S_K * WPITCH * 4);
#pragma unroll
        for (int j = 0; j < 4; j++)
            cp_async16(dst + j * (8 * WPITCH * 4), src + (size_t)(8 * j) * NDIM);
    };
    auto load_act = [&](int kc) {
#pragma unroll
        for (int i = tid; i < MDIM * (K_CHUNK / 8); i += THREADS) {
            const int r = i >> 5;       // K_CHUNK/8 == 32
            const int c = i & 31;
            *reinterpret_cast<int4*>(&sA[r][c * 8]) =
                *reinterpret_cast<const int4*>(g_actH + (size_t)r * KDIM + kc + c * 8);
        }
    };
    auto compute_stage = [&](int buf, int choff) {
        const int* wb = &sW[buf][0];
#pragma unroll
        for (int kk = 0; kk < S_K; kk += 16) {
            uint32_t afrag0[4], afrag1[4];
            ldsm_x4(afrag0, addrA0 + (choff + kk) * 2);
            ldsm_x4(afrag1, addrA1 + (choff + kk) * 2);
#pragma unroll
            for (int nt = 0; nt < 2; nt++) {
                const int* p = wb + kk * WPITCH + boff + nt * 8;
                const int w0 = p[0];
                const int w1 = p[WPITCH];
                const int w2 = p[8 * WPITCH];
                const int w3 = p[9 * WPITCH];
                const uint32_t b0 = cvt_w2(w0, w1);
                const uint32_t b1 = cvt_w2(w2, w3);
                mma16816(acc[0][nt], afrag0, b0, b1);
                mma16816(acc[1][nt], afrag1, b0, b1);
            }
        }
    };

    // --- prologue: 3 weight stages in flight + act chunk 0
    cp_stage(kbase + 0 * S_K, 0); asm volatile("cp.async.commit_group;");
    cp_stage(kbase + 1 * S_K, 1); asm volatile("cp.async.commit_group;");
    cp_stage(kbase + 2 * S_K, 2); asm volatile("cp.async.commit_group;");
    load_act(kbase);
    asm volatile("cp.async.wait_group 2;");
    __syncthreads();

#pragma unroll 1
    for (int st = 0; st < TOTAL_STAGES; st++) {
        const int pf = st + 3;
        if (pf < TOTAL_STAGES) cp_stage(kbase + pf * S_K, pf & (NBUF - 1));
        asm volatile("cp.async.commit_group;");
        compute_stage(st & (NBUF - 1), (st & 7) * S_K);
        asm volatile("cp.async.wait_group 2;");
        __syncthreads();
        if (((st + 1) & 7) == 0 && st + 1 < TOTAL_STAGES) {
            load_act(kbase + (st + 1) * S_K);
            __syncthreads();
        }
    }

    // --- write unscaled partials
    float* part = g_partial[kz];
#pragma unroll
    for (int mt = 0; mt < 2; mt++) {
#pragma unroll
        for (int nt = 0; nt < 2; nt++) {
            const int col = nblk + warp * 16 + nt * 8 + 2 * tig;
            const int r0 = mt * 16 + gid;
#pragma unroll
            for (int hr = 0; hr < 2; hr++) {
                const int r = r0 + hr * 8;
                float2 o;
                o.x = acc[mt][nt][hr * 2 + 0];
                o.y = acc[mt][nt][hr * 2 + 1];
                *reinterpret_cast<float2*>(part + (size_t)r * NDIM + col) = o;
            }
        }
    }
}

// ---------------------------------------------------------------------------
// One-shot act f32 -> fp16 (lossless: values are exact fp16)
__global__ void __launch_bounds__(256)
act_cvt_kernel(const float* __restrict__ act) {
    const int i = blockIdx.x * blockDim.x + threadIdx.x;   // per float4
    const float4 v = reinterpret_cast<const float4*>(act)[i];
    __half2* dst = reinterpret_cast<__half2*>(g_actH) + i * 2;
    dst[0] = __floats2half2_rn(v.x, v.y);
    dst[1] = __floats2half2_rn(v.z, v.w);
}

// Reduce split-K partials, apply scale, round through fp16, emit f32.
__global__ void __launch_bounds__(256)
reduce_kernel(const float* __restrict__ scale, float* __restrict__ out) {
    const int idx = blockIdx.x * blockDim.x + threadIdx.x;   // per float4
    const size_t off = (size_t)idx * 4;
    if (off >= (size_t)MDIM * NDIM) return;

    float4 s = *reinterpret_cast<const float4*>(&g_partial[0][off]);
#pragma unroll
    for (int p = 1; p < KSPLIT; p++) {
        const float4 q = *reinterpret_cast<const float4*>(&g_partial[p][off]);
        s.x += q.x; s.y += q.y; s.z += q.z; s.w += q.w;
    }

    const int col = (int)(off % NDIM);
    const float4 sc = *reinterpret_cast<const float4*>(scale + col);

    float4 o;
    o.x = __half2float(__float2half_rn(s.x * sc.x));
    o.y = __half2float(__float2half_rn(s.y * sc.y));
    o.z = __half2float(__float2half_rn(s.z * sc.z));
    o.w = __half2float(__float2half_rn(s.w * sc.w));
    *reinterpret_cast<float4*>(out + off) = o;
}

// ---------------------------------------------------------------------------
extern "C" void kernel_launch(void* const* d_in, const int* in_sizes, int n_in,
                              void* d_out, int out_size) {
    const float* act    = (const float*)d_in[0];   // [32, 8192] f32
    const int*   weight = (const int*)d_in[1];     // [8192, 28672] int32
    const float* scale  = (const float*)d_in[2];   // [28672] f32
    float*       out    = (float*)d_out;           // [32, 28672] f32

    act_cvt_kernel<<<(MDIM * KDIM / 4) / 256, 256>>>(act);

    dim3 grid(NDIM / N_TILE, KSPLIT);
    dq_gemm_partial_kernel<<<grid, THREADS>>>(weight);

    const int total4 = (MDIM * NDIM) / 4;          // 229376
    reduce_kernel<<<(total4 + 255) / 256, 256>>>(scale, out);
}

// round 6
// speedup vs baseline: 2.4418x; 1.1233x over previous
#include <cuda_runtime.h>
#include <cuda_fp16.h>
#include <cstdint>

// Problem constants
#define MDIM 32
#define KDIM 8192
#define NDIM 28672
#define N_TILE 64                 // n-columns per CTA (4 warps x 16)
#define THREADS 128
#define KSPLIT 4
#define K_PER_SPLIT (KDIM / KSPLIT)       // 2048
#define S_K 32                            // weight k-rows per pipeline stage
#define NBUF 3                            // per-warp cp.async ring depth
#define TOTAL_STAGES (K_PER_SPLIT / S_K)  // 64
#define K_CHUNK 256                       // act chunk (8 stages)
#define APAD 8
#define WPITCH 20                         // int32 words per k-row in a warp tile (16+4)
#define WARP_STAGE_WORDS (S_K * WPITCH)   // 640 words = 2560 B

// Scratch: split-K fp32 partials (14.7 MB) + fp16 act copy (512 KB)
__device__ float  g_partial[KSPLIT][MDIM * NDIM];
__device__ __half g_actH[MDIM * KDIM];

// ---------------------------------------------------------------------------
__device__ __forceinline__ void mma16816(float c[4], const uint32_t a[4],
                                         uint32_t b0, uint32_t b1) {
    asm volatile(
        "mma.sync.aligned.m16n8k16.row.col.f32.f16.f16.f32 "
        "{%0,%1,%2,%3}, {%4,%5,%6,%7}, {%8,%9}, {%0,%1,%2,%3};"
        : "+f"(c[0]), "+f"(c[1]), "+f"(c[2]), "+f"(c[3])
        : "r"(a[0]), "r"(a[1]), "r"(a[2]), "r"(a[3]), "r"(b0), "r"(b1));
}

__device__ __forceinline__ void ldsm_x4(uint32_t a[4], uint32_t smem_addr) {
    asm volatile(
        "ldmatrix.sync.aligned.m8n8.x4.shared.b16 {%0,%1,%2,%3}, [%4];"
        : "=r"(a[0]), "=r"(a[1]), "=r"(a[2]), "=r"(a[3])
        : "r"(smem_addr));
}

// Two int32 weights (in [-127,127]) -> packed half2 {w0, w1}. Exact.
__device__ __forceinline__ uint32_t cvt_w2(int w0, int w1) {
    uint32_t t, h;
    asm("prmt.b32 %0, %1, %2, 0x0400;" : "=r"(t) : "r"(w0), "r"(w1));
    asm("lop3.b32 %0, %1, %2, %3, 0x6A;"            // (a & b) ^ c
        : "=r"(h) : "r"(t), "n"(0x00FF00FF), "n"(0x64806480));
    const uint32_t bias = 0x64806480u;               // half2(1152, 1152)
    __half2 hv = __hsub2(*reinterpret_cast<__half2*>(&h),
                         *reinterpret_cast<const __half2*>(&bias));
    return *reinterpret_cast<uint32_t*>(&hv);
}

__device__ __forceinline__ void cp_async16(uint32_t smem_dst, const void* gsrc) {
    asm volatile("cp.async.cg.shared.global [%0], [%1], 16;\n"
                 :: "r"(smem_dst), "l"(gsrc));
}
__device__ __forceinline__ void cp_commit() {
    asm volatile("cp.async.commit_group;");
}
__device__ __forceinline__ void cp_wait2() {
    asm volatile("cp.async.wait_group 2;");
}

// ---------------------------------------------------------------------------
__global__ void __launch_bounds__(THREADS)
dq_gemm_partial_kernel(const int* __restrict__ weight)   // int32 (int8 values)
{
    __shared__ __half sA[MDIM][K_CHUNK + APAD];                 // 16.9 KB
    __shared__ int    sW[4][NBUF][WARP_STAGE_WORDS];            // 30.7 KB (per-warp rings)

    const int tid  = threadIdx.x;
    const int warp = tid >> 5;
    const int lane = tid & 31;
    const int gid  = lane >> 2;   // 0..7
    const int tig  = lane & 3;    // 0..3

    const int nblk  = blockIdx.x * N_TILE;
    const int kz    = blockIdx.y;
    const int kbase = kz * K_PER_SPLIT;

    float acc[2][2][4];
#pragma unroll
    for (int i = 0; i < 2; i++)
#pragma unroll
        for (int j = 0; j < 2; j++)
#pragma unroll
            for (int c = 0; c < 4; c++) acc[i][j][c] = 0.0f;

    // A-side ldmatrix addresses
    const int lrow = lane & 15;
    const int lcol = (lane >> 4) * 8;
    const uint32_t sA_base = (uint32_t)__cvta_generic_to_shared(&sA[0][0]);
    const uint32_t rowbytesA = (K_CHUNK + APAD) * 2;
    const uint32_t addrA0 = sA_base + lrow * rowbytesA + lcol * 2;         // m 0-15
    const uint32_t addrA1 = sA_base + (16 + lrow) * rowbytesA + lcol * 2;  // m 16-31

    // Per-warp weight cp.async: warp owns cols [warp*16, warp*16+16).
    // lane -> row (lane>>2)+8j, col-chunk (lane&3)*4 within the warp's 16 cols.
    const int crow = lane >> 2;         // 0..7
    const int ccol = (lane & 3) * 4;    // 0,4,8,12
    const int* wsrc = weight + (size_t)crow * NDIM + nblk + warp * 16 + ccol;
    const uint32_t sWw_base = (uint32_t)__cvta_generic_to_shared(&sW[warp][0][0]);
    const uint32_t cp_dst0 = sWw_base + (uint32_t)((crow * WPITCH + ccol) * 4);

    // B-fragment LDS base word offset within a stage buffer
    const int boff = 2 * tig * WPITCH + gid;
    const int* wbase = &sW[warp][0][0];

    auto cp_stage = [&](int k0, int buf) {
        const int* src = wsrc + (size_t)k0 * NDIM;
        const uint32_t dst = cp_dst0 + (uint32_t)(buf * WARP_STAGE_WORDS * 4);
#pragma unroll
        for (int j = 0; j < 4; j++)
            cp_async16(dst + j * (8 * WPITCH * 4), src + (size_t)(8 * j) * NDIM);
    };
    auto load_act = [&](int kc) {
#pragma unroll
        for (int i = tid; i < MDIM * (K_CHUNK / 8); i += THREADS) {
            const int r = i >> 5;       // K_CHUNK/8 == 32
            const int c = i & 31;
            *reinterpret_cast<int4*>(&sA[r][c * 8]) =
                *reinterpret_cast<const int4*>(g_actH + (size_t)r * KDIM + kc + c * 8);
        }
    };
    auto compute_stage = [&](int buf, int choff) {
        const int* wb = wbase + buf * WARP_STAGE_WORDS;
#pragma unroll
        for (int kk = 0; kk < S_K; kk += 16) {
            uint32_t afrag0[4], afrag1[4];
            ldsm_x4(afrag0, addrA0 + (choff + kk) * 2);
            ldsm_x4(afrag1, addrA1 + (choff + kk) * 2);
#pragma unroll
            for (int nt = 0; nt < 2; nt++) {
                const int* p = wb + kk * WPITCH + boff + nt * 8;
                const int w0 = p[0];
                const int w1 = p[WPITCH];
                const int w2 = p[8 * WPITCH];
                const int w3 = p[9 * WPITCH];
                const uint32_t b0 = cvt_w2(w0, w1);
                const uint32_t b1 = cvt_w2(w2, w3);
                mma16816(acc[0][nt], afrag0, b0, b1);
                mma16816(acc[1][nt], afrag1, b0, b1);
            }
        }
    };

    // --- prologue: 3 per-warp weight stages in flight + act chunk 0
    cp_stage(kbase + 0 * S_K, 0); cp_commit();
    cp_stage(kbase + 1 * S_K, 1); cp_commit();
    cp_stage(kbase + 2 * S_K, 2); cp_commit();
    load_act(kbase);
    __syncthreads();

    int buf = 0;
#pragma unroll 1
    for (int st = 0; st < TOTAL_STAGES; st++) {
        if ((st & 7) == 0 && st > 0) {
            __syncthreads();                  // all warps done with prev act chunk
            load_act(kbase + st * S_K);
            __syncthreads();
        }
        cp_wait2();                           // group st (== stage st) resident
        compute_stage(buf, (st & 7) * S_K);
        const int pf = st + 3;
        if (pf < TOTAL_STAGES) cp_stage(kbase + pf * S_K, buf);
        cp_commit();                          // commit every iter (empty at tail)
        buf = (buf == NBUF - 1) ? 0 : buf + 1;
    }

    // --- write unscaled partials
    float* part = g_partial[kz];
#pragma unroll
    for (int mt = 0; mt < 2; mt++) {
#pragma unroll
        for (int nt = 0; nt < 2; nt++) {
            const int col = nblk + warp * 16 + nt * 8 + 2 * tig;
            const int r0 = mt * 16 + gid;
#pragma unroll
            for (int hr = 0; hr < 2; hr++) {
                const int r = r0 + hr * 8;
                float2 o;
                o.x = acc[mt][nt][hr * 2 + 0];
                o.y = acc[mt][nt][hr * 2 + 1];
                *reinterpret_cast<float2*>(part + (size_t)r * NDIM + col) = o;
            }
        }
    }
}

// ---------------------------------------------------------------------------
// One-shot act f32 -> fp16 (lossless: values are exact fp16)
__global__ void __launch_bounds__(256)
act_cvt_kernel(const float* __restrict__ act) {
    const int i = blockIdx.x * blockDim.x + threadIdx.x;   // per float4
    const float4 v = reinterpret_cast<const float4*>(act)[i];
    __half2* dst = reinterpret_cast<__half2*>(g_actH) + i * 2;
    dst[0] = __floats2half2_rn(v.x, v.y);
    dst[1] = __floats2half2_rn(v.z, v.w);
}

// Reduce split-K partials, apply scale, round through fp16, emit f32.
__global__ void __launch_bounds__(256)
reduce_kernel(const float* __restrict__ scale, float* __restrict__ out) {
    const int idx = blockIdx.x * blockDim.x + threadIdx.x;   // per float4
    const size_t off = (size_t)idx * 4;
    if (off >= (size_t)MDIM * NDIM) return;

    float4 s = *reinterpret_cast<const float4*>(&g_partial[0][off]);
#pragma unroll
    for (int p = 1; p < KSPLIT; p++) {
        const float4 q = *reinterpret_cast<const float4*>(&g_partial[p][off]);
        s.x += q.x; s.y += q.y; s.z += q.z; s.w += q.w;
    }

    const int col = (int)(off % NDIM);
    const float4 sc = *reinterpret_cast<const float4*>(scale + col);

    float4 o;
    o.x = __half2float(__float2half_rn(s.x * sc.x));
    o.y = __half2float(__float2half_rn(s.y * sc.y));
    o.z = __half2float(__float2half_rn(s.z * sc.z));
    o.w = __half2float(__float2half_rn(s.w * sc.w));
    *reinterpret_cast<float4*>(out + off) = o;
}

// ---------------------------------------------------------------------------
extern "C" void kernel_launch(void* const* d_in, const int* in_sizes, int n_in,
                              void* d_out, int out_size) {
    const float* act    = (const float*)d_in[0];   // [32, 8192] f32
    const int*   weight = (const int*)d_in[1];     // [8192, 28672] int32
    const float* scale  = (const float*)d_in[2];   // [28672] f32
    float*       out    = (float*)d_out;           // [32, 28672] f32

    act_cvt_kernel<<<(MDIM * KDIM / 4) / 256, 256>>>(act);

    dim3 grid(NDIM / N_TILE, KSPLIT);
    dq_gemm_partial_kernel<<<grid, THREADS>>>(weight);

    const int total4 = (MDIM * NDIM) / 4;          // 229376
    reduce_kernel<<<(total4 + 255) / 256, 256>>>(scale, out);
}